// round 14
// baseline (speedup 1.0000x reference)
#include <cuda_runtime.h>
#include <cuda_fp16.h>
#include <math.h>
#include <string.h>
#include <stdint.h>

#define BB 4
#define SS_ 1024
#define DD 512
#define HH 8
#define DKK 64
#define PP_ 2047
#define PPAD 2048
#define PBAND 2304

typedef __half half_t;

// ---------------- scratch (zero-initialized device globals) ----------------
__device__ half_t g_xf[BB*SS_*DD];
__device__ half_t g_pef[PPAD*DD];
__device__ half_t g_wf[5*DD*DD];
__device__ half_t g_quf[BB*SS_*DD], g_qvf[BB*SS_*DD];
__device__ half_t g_kf[BB*SS_*DD],  g_vf[BB*SS_*DD];
__device__ half_t g_pf[(size_t)PBAND*DD];   // rows >= 2047 stay zero
__device__ half_t g_tf[BB*SS_*DD];

// ---------------- helpers ----------------
__device__ __forceinline__ void mma16816(float* d, const uint32_t* a, const uint32_t* b){
    asm volatile("mma.sync.aligned.m16n8k16.row.col.f32.f16.f16.f32 "
        "{%0,%1,%2,%3}, {%4,%5,%6,%7}, {%8,%9}, {%0,%1,%2,%3};"
        : "+f"(d[0]),"+f"(d[1]),"+f"(d[2]),"+f"(d[3])
        : "r"(a[0]),"r"(a[1]),"r"(a[2]),"r"(a[3]), "r"(b[0]),"r"(b[1]));
}
__device__ __forceinline__ void ldsm4(uint32_t* r, uint32_t addr){
    asm volatile("ldmatrix.sync.aligned.m8n8.x4.shared.b16 {%0,%1,%2,%3}, [%4];"
        :"=r"(r[0]),"=r"(r[1]),"=r"(r[2]),"=r"(r[3]):"r"(addr));
}
__device__ __forceinline__ void ldsm4t(uint32_t* r, uint32_t addr){
    asm volatile("ldmatrix.sync.aligned.m8n8.x4.trans.shared.b16 {%0,%1,%2,%3}, [%4];"
        :"=r"(r[0]),"=r"(r[1]),"=r"(r[2]),"=r"(r[3]):"r"(addr));
}
__device__ __forceinline__ uint32_t smem_u32(const void* p){
    uint32_t a; asm("{ .reg .u64 t; cvta.to.shared.u64 t, %1; cvt.u32.u64 %0, t; }":"=r"(a):"l"(p)); return a;
}
__device__ __forceinline__ void cp16(uint32_t dst, const void* src){
    asm volatile("cp.async.cg.shared.global [%0], [%1], 16;"
        :: "r"(dst), "l"(__cvta_generic_to_global(src)));
}
#define CP_COMMIT() asm volatile("cp.async.commit_group;" ::: "memory")
#define CP_WAIT1()  asm volatile("cp.async.wait_group 1;" ::: "memory")
#define CP_WAIT2()  asm volatile("cp.async.wait_group 2;" ::: "memory")
static __device__ __forceinline__ uint32_t swz(uint32_t o){ return o ^ ((o>>3)&0x70); }
__device__ __forceinline__ uint32_t a_addr(uint32_t base, int m16, int k0, int lane){
    int g = lane>>3, r = lane&7;
    int row = m16 + r + (g&1)*8;
    uint32_t o = (uint32_t)(row*128 + (k0 + (g>>1)*8)*2);
    return base + swz(o);
}
__device__ __forceinline__ uint32_t b_addr(uint32_t base, int n0, int k0, int lane){
    int g = lane>>3, r = lane&7;
    int row = n0 + r + (g>>1)*8;
    uint32_t o = (uint32_t)(row*128 + (k0 + (g&1)*8)*2);
    return base + swz(o);
}
__device__ __forceinline__ uint32_t v_addr(uint32_t base, int k0, int d0, int lane){
    int g = lane>>3, r = lane&7;
    int row = k0 + r + (g&1)*8;
    uint32_t o = (uint32_t)(row*128 + (d0 + (g>>1)*8)*2);
    return base + swz(o);
}
__device__ __forceinline__ uint32_t packh(float x, float y){
    __half2 h = __floats2half2_rn(x, y);
    uint32_t u; memcpy(&u, &h, 4); return u;
}

// ================= prep: LN + PE + weight converts, one launch =================
__global__ void prep_kernel(const float* __restrict__ x, const float* __restrict__ gamma,
                            const float* __restrict__ beta,
                            const float* __restrict__ Wq, const float* __restrict__ Wk,
                            const float* __restrict__ Wv, const float* __restrict__ Wo,
                            const float* __restrict__ Wp,
                            half_t* __restrict__ xf, half_t* __restrict__ pef,
                            half_t* __restrict__ wf) {
    __shared__ float red[8];
    const int blk = blockIdx.x, tid = threadIdx.x;
    if (blk < 2048) {
        int halfid = tid >> 7, t = tid & 127;
        int row = blk*2 + halfid;
        float4 v = ((const float4*)(x + (size_t)row*DD))[t];
        float s = v.x+v.y+v.z+v.w;
        #pragma unroll
        for (int o=16;o;o>>=1) s += __shfl_xor_sync(0xffffffffu,s,o);
        if ((t&31)==0) red[tid>>5]=s;
        __syncthreads();
        float mu=(red[halfid*4]+red[halfid*4+1]+red[halfid*4+2]+red[halfid*4+3])*(1.0f/DD);
        float dx=v.x-mu,dy=v.y-mu,dz=v.z-mu,dw=v.w-mu;
        float ss=dx*dx+dy*dy+dz*dz+dw*dw;
        #pragma unroll
        for (int o=16;o;o>>=1) ss += __shfl_xor_sync(0xffffffffu,ss,o);
        __syncthreads();
        if ((t&31)==0) red[tid>>5]=ss;
        __syncthreads();
        float rstd=rsqrtf((red[halfid*4]+red[halfid*4+1]+red[halfid*4+2]+red[halfid*4+3])*(1.0f/DD)+1e-5f);
        float4 g=((const float4*)gamma)[t], be=((const float4*)beta)[t];
        uint2 o2;
        o2.x = packh(dx*rstd*g.x+be.x, dy*rstd*g.y+be.y);
        o2.y = packh(dz*rstd*g.z+be.z, dw*rstd*g.w+be.w);
        *(uint2*)(xf + (size_t)row*DD + 4*t) = o2;
    } else if (blk < 4096) {
        int j = blk - 2048;
        uint32_t u = 0;
        if (j < PP_) {
            float pos = (float)(j - (SS_ - 1));
            const float kconst = -0.01798894603901598415f;
            float div = expf((float)(2*tid) * kconst);
            float sa, ca; sincosf(pos * div, &sa, &ca);
            u = packh(sa, ca);
        }
        *(uint32_t*)(pef + (size_t)j*DD + 2*tid) = u;
    } else {
        int i = (blk - 4096)*256 + tid;
        int widx = i >> 16, j = i & 65535;
        const float* src = (widx==0)?Wq:(widx==1)?Wk:(widx==2)?Wv:(widx==3)?Wo:Wp;
        float4 v = ((const float4*)src)[j];
        uint2 o2; o2.x = packh(v.x, v.y); o2.y = packh(v.z, v.w);
        ((uint2*)(wf + (size_t)widx*DD*DD))[j] = o2;
    }
}

// ================= fused projections: QKV (N=1536) + P, 2-stage (best) =================
__global__ __launch_bounds__(256,2) void proj_all(
    const half_t* __restrict__ xf, const half_t* __restrict__ pef,
    const half_t* __restrict__ wf,
    const float* __restrict__ bq, const float* __restrict__ bk, const float* __restrict__ bv,
    const float* __restrict__ pu, const float* __restrict__ pv,
    half_t* __restrict__ quf, half_t* __restrict__ qvf,
    half_t* __restrict__ kf, half_t* __restrict__ vf, half_t* __restrict__ pf)
{
    extern __shared__ char sm[];
    const int tid = threadIdx.x, lane = tid & 31, wid = tid >> 5;
    const uint32_t sb = smem_u32(sm);
    const int m0w = (wid>>2)*64, n0w = (wid&3)*32;
    const int cta = blockIdx.x;
    const half_t *A, *B;
    int bm, bn, mode;
    if (cta < 384) {
        int bx = cta % 12, by = cta / 12;
        bm = by*128; bn = bx*128;
        A = xf; B = wf + (size_t)bn*DD;
        mode = bn >> 9;
    } else {
        int c2 = cta - 384;
        int bx = c2 & 3, by = c2 >> 2;
        bm = by*128; bn = bx*128;
        A = pef; B = wf + 4*(size_t)DD*DD + (size_t)bn*DD;
        mode = 3;
    }

    auto issueg = [&](int kc){
        uint32_t base = sb + (uint32_t)(kc&1)*32768;
        for (int u = tid; u < 1024; u += 256) {
            int row = u>>3, cb = u&7;
            uint32_t off = swz((uint32_t)(row*128 + cb*16));
            cp16(base + off,         A + (size_t)(bm+row)*DD + kc*64 + cb*8);
            cp16(base + 16384 + off, B + (size_t)row*DD + kc*64 + cb*8);
        }
    };

    float acc[4][4][4];
    #pragma unroll
    for (int a=0;a<4;++a)
        #pragma unroll
        for (int b2=0;b2<4;++b2)
            #pragma unroll
            for (int c2=0;c2<4;++c2) acc[a][b2][c2]=0.f;

    issueg(0); CP_COMMIT();
    issueg(1); CP_COMMIT();

    for (int kc = 0; kc < 8; ++kc) {
        CP_WAIT1();
        __syncthreads();
        uint32_t base = sb + (uint32_t)(kc&1)*32768;
        #pragma unroll
        for (int ks = 0; ks < 4; ++ks) {
            int k0 = ks*16;
            uint32_t aF[4][4], bF[2][4];
            #pragma unroll
            for (int mt=0; mt<4; ++mt) ldsm4(aF[mt], a_addr(base, m0w+mt*16, k0, lane));
            #pragma unroll
            for (int p=0; p<2; ++p)   ldsm4(bF[p], b_addr(base+16384, n0w+p*16, k0, lane));
            #pragma unroll
            for (int mt=0; mt<4; ++mt)
                #pragma unroll
                for (int nt=0; nt<4; ++nt)
                    mma16816(acc[mt][nt], aF[mt], &bF[nt>>1][(nt&1)*2]);
        }
        __syncthreads();
        if (kc + 2 < 8) issueg(kc + 2);
        CP_COMMIT();
    }
    const int r = lane>>2, c = (lane&3)*2;
    const int nbase = bn & 511;
    #pragma unroll
    for (int mt=0; mt<4; ++mt)
        #pragma unroll
        for (int nt=0; nt<4; ++nt) {
            int nl = nbase + n0w + nt*8 + c;
            float b0 = 0.f, b1 = 0.f;
            if (mode == 0)      { b0 = bq[nl]; b1 = bq[nl+1]; }
            else if (mode == 1) { b0 = bk[nl]; b1 = bk[nl+1]; }
            else if (mode == 2) { b0 = bv[nl]; b1 = bv[nl+1]; }
            #pragma unroll
            for (int half_=0; half_<2; ++half_) {
                int m_ = bm + m0w + mt*16 + r + half_*8;
                float v0 = acc[mt][nt][half_*2+0] + b0;
                float v1 = acc[mt][nt][half_*2+1] + b1;
                if (mode == 0) {
                    *(uint32_t*)(quf + (size_t)m_*DD + nl) = packh(v0 + pu[nl], v1 + pu[nl+1]);
                    *(uint32_t*)(qvf + (size_t)m_*DD + nl) = packh(v0 + pv[nl], v1 + pv[nl+1]);
                } else if (mode == 1) {
                    *(uint32_t*)(kf + (size_t)m_*DD + nl) = packh(v0, v1);
                } else if (mode == 2) {
                    *(uint32_t*)(vf + (size_t)m_*DD + nl) = packh(v0, v1);
                } else {
                    *(uint32_t*)(pf + (size_t)m_*DD + nl) = packh(v0, v1);
                }
            }
        }
}

// ================= out projection: 128x128 tiles, 3-stage (best) =================
__global__ __launch_bounds__(256,2) void gemm_out(
    const half_t* __restrict__ A, const half_t* __restrict__ Bw,
    const float* __restrict__ bias, float* __restrict__ O32)
{
    extern __shared__ char sm[];
    const int tid = threadIdx.x, lane = tid & 31, wid = tid >> 5;
    const int bm = blockIdx.y * 128, bn = blockIdx.x * 128;
    const uint32_t sb = smem_u32(sm);
    const int m0w = (wid>>2)*64, n0w = (wid&3)*32;

    auto issueg = [&](int kc){
        uint32_t base = sb + (uint32_t)(kc%3)*32768;
        for (int u = tid; u < 1024; u += 256) {
            int row = u>>3, cb = u&7;
            uint32_t off = swz((uint32_t)(row*128 + cb*16));
            cp16(base + off,         A  + (size_t)(bm+row)*DD + kc*64 + cb*8);
            cp16(base + 16384 + off, Bw + (size_t)(bn+row)*DD + kc*64 + cb*8);
        }
    };

    float acc[4][4][4];
    #pragma unroll
    for (int a=0;a<4;++a)
        #pragma unroll
        for (int b2=0;b2<4;++b2)
            #pragma unroll
            for (int c2=0;c2<4;++c2) acc[a][b2][c2]=0.f;

    issueg(0); CP_COMMIT();
    issueg(1); CP_COMMIT();
    issueg(2); CP_COMMIT();

    for (int kc = 0; kc < 8; ++kc) {
        CP_WAIT2();
        __syncthreads();
        uint32_t base = sb + (uint32_t)(kc%3)*32768;
        #pragma unroll
        for (int ks = 0; ks < 4; ++ks) {
            int k0 = ks*16;
            uint32_t aF[4][4], bF[2][4];
            #pragma unroll
            for (int mt=0; mt<4; ++mt) ldsm4(aF[mt], a_addr(base, m0w+mt*16, k0, lane));
            #pragma unroll
            for (int p=0; p<2; ++p)   ldsm4(bF[p], b_addr(base+16384, n0w+p*16, k0, lane));
            #pragma unroll
            for (int mt=0; mt<4; ++mt)
                #pragma unroll
                for (int nt=0; nt<4; ++nt)
                    mma16816(acc[mt][nt], aF[mt], &bF[nt>>1][(nt&1)*2]);
        }
        __syncthreads();
        if (kc + 3 < 8) issueg(kc + 3);
        CP_COMMIT();
    }
    const int r = lane>>2, c = (lane&3)*2;
    #pragma unroll
    for (int mt=0; mt<4; ++mt)
        #pragma unroll
        for (int nt=0; nt<4; ++nt) {
            int n_ = bn + n0w + nt*8 + c;
            float b0 = bias[n_], b1 = bias[n_+1];
            #pragma unroll
            for (int half_=0; half_<2; ++half_) {
                int m_ = bm + m0w + mt*16 + r + half_*8;
                *(float2*)(O32 + (size_t)m_*DD + n_) =
                    make_float2(acc[mt][nt][half_*2+0] + b0, acc[mt][nt][half_*2+1] + b1);
            }
        }
}

// ================= fused attention: 64-row q-tiles, 128 thr, 2 CTA/SM =================
#define AQ_V   8192
#define AP_BUF 16384
#define AK_BUF 40960
#define AV_BUF 57344
#define ABD    73728
#define ASMEM  107520
__global__ __launch_bounds__(128,2) void attn_fused(
    const half_t* __restrict__ quf, const half_t* __restrict__ qvf,
    const half_t* __restrict__ kf,  const half_t* __restrict__ vf,
    const half_t* __restrict__ pf,
    const unsigned char* __restrict__ mask,
    half_t* __restrict__ tf)
{
    extern __shared__ char sm[];
    const int tid = threadIdx.x, lane = tid & 31, wid = tid >> 5;
    const int bh = blockIdx.y, b = bh >> 3, h = bh & 7;
    const int qc = blockIdx.x * 64;
    const uint32_t sb = smem_u32(sm);
    float* bd = (float*)(sm + ABD);
    const int wq = wid * 16;
    const int r = lane>>2, c = (lane&3)*2;

    auto issue = [&](int st){
        int ch = st >> 1;
        if ((st & 1) == 0) {
            size_t rowbase = (size_t)(1024 + 128*ch - qc - 63);
            for (int u = tid; u < 1536; u += 128){
                int row = u>>3, cb = u&7;
                cp16(sb + AP_BUF + swz((uint32_t)(row*128 + cb*16)),
                     pf + (rowbase + row)*DD + h*DKK + cb*8);
            }
        } else {
            size_t rowbase = (size_t)(b*SS_ + 128*ch);
            for (int u = tid; u < 1024; u += 128){
                int row = u>>3, cb = u&7;
                uint32_t off = swz((uint32_t)(row*128 + cb*16));
                cp16(sb + AK_BUF + off, kf + (rowbase + row)*DD + h*DKK + cb*8);
                cp16(sb + AV_BUF + off, vf + (rowbase + row)*DD + h*DKK + cb*8);
            }
        }
    };

    for (int u = tid; u < 512; u += 128) {
        int row = u>>3, cb = u&7;
        uint32_t off = swz((uint32_t)(row*128 + cb*16));
        size_t g = (size_t)(b*SS_ + qc + row)*DD + h*DKK + cb*8;
        cp16(sb + off,        quf + g);
        cp16(sb + AQ_V + off, qvf + g);
    }
    issue(0); CP_COMMIT();
    issue(1); CP_COMMIT();

    float wrapv = 0.f;
    if (qc == 0 && wid == 0) {
        #pragma unroll
        for (int d = 0; d < DKK; ++d)
            wrapv += __half2float(qvf[(size_t)(b*SS_+1)*DD + h*DKK + d])
                   * __half2float(pf[h*DKK + d]);
    }

    float m0 = -1e30f, m1 = -1e30f, l0 = 0.f, l1 = 0.f;
    float accO[8][4];
    #pragma unroll
    for (int i=0;i<8;++i)
        #pragma unroll
        for (int j=0;j<4;++j) accO[i][j]=0.f;

    const int i0 = wq + r, i1 = i0 + 8;
    const int bd0base = i0*132, bd1base = i1*132;

    for (int st = 0; st < 16; ++st) {
        CP_WAIT1();
        __syncthreads();
        const int ch = st >> 1;

        if ((st & 1) == 0) {
            float bdacc[9][2][4];
            #pragma unroll
            for (int gi=0;gi<9;++gi)
                #pragma unroll
                for (int q2=0;q2<2;++q2)
                    #pragma unroll
                    for (int e=0;e<4;++e) bdacc[gi][q2][e]=0.f;
            #pragma unroll
            for (int ks = 0; ks < 4; ++ks) {
                int k0 = ks*16;
                uint32_t aF[4];
                ldsm4(aF, a_addr(sb + AQ_V, wq, k0, lane));
                #pragma unroll
                for (int gi = 0; gi < 9; ++gi) {
                    int n0 = (3 - wid + gi)*16;
                    uint32_t bF[4];
                    ldsm4(bF, b_addr(sb + AP_BUF, n0, k0, lane));
                    mma16816(bdacc[gi][0], aF, &bF[0]);
                    mma16816(bdacc[gi][1], aF, &bF[2]);
                }
            }
            #pragma unroll
            for (int gi = 0; gi < 9; ++gi) {
                int g16 = 3 - wid + gi;
                #pragma unroll
                for (int q2 = 0; q2 < 2; ++q2) {
                    int t0 = g16*16 + q2*8 + c;
                    int j;
                    j = t0     + i0 - 63; if (j>=0 && j<128) bd[bd0base+j] = bdacc[gi][q2][0];
                    j = t0 + 1 + i0 - 63; if (j>=0 && j<128) bd[bd0base+j] = bdacc[gi][q2][1];
                    j = t0     + i1 - 63; if (j>=0 && j<128) bd[bd1base+j] = bdacc[gi][q2][2];
                    j = t0 + 1 + i1 - 63; if (j>=0 && j<128) bd[bd1base+j] = bdacc[gi][q2][3];
                }
            }
        } else {
            const int kk0 = ch * 128;

            // hoisted mask prefetch
            uchar2 mq0a[16], mq1a[16];
            {
                const unsigned char* mb0 = mask + (size_t)b*SS_*SS_ + (size_t)(qc+i0)*SS_ + kk0;
                const unsigned char* mb1 = mask + (size_t)b*SS_*SS_ + (size_t)(qc+i1)*SS_ + kk0;
                #pragma unroll
                for (int nt = 0; nt < 16; ++nt) {
                    int jc = nt*8 + c;
                    mq0a[nt] = *(const uchar2*)(mb0 + jc);
                    mq1a[nt] = *(const uchar2*)(mb1 + jc);
                }
            }

            float s[16][4];
            #pragma unroll
            for (int nt=0;nt<16;++nt)
                #pragma unroll
                for (int e=0;e<4;++e) s[nt][e]=0.f;
            #pragma unroll
            for (int ks = 0; ks < 4; ++ks) {
                int k0 = ks*16;
                uint32_t aF[4];
                ldsm4(aF, a_addr(sb, wq, k0, lane));
                #pragma unroll
                for (int g16 = 0; g16 < 8; ++g16) {
                    uint32_t bF[4];
                    ldsm4(bF, b_addr(sb + AK_BUF, g16*16, k0, lane));
                    mma16816(s[2*g16],   aF, &bF[0]);
                    mma16816(s[2*g16+1], aF, &bF[2]);
                }
            }
            float mc0 = -1e30f, mc1 = -1e30f;
            #pragma unroll
            for (int nt = 0; nt < 16; ++nt) {
                int jc = nt*8 + c;
                // vectorized bd reads (8B-aligned: jc even, row base even)
                float2 bdv0 = *(const float2*)&bd[bd0base + jc];
                float2 bdv1 = *(const float2*)&bd[bd1base + jc];
                float v0 = s[nt][0] + bdv0.x;
                float v1 = s[nt][1] + bdv0.y;
                float v2 = s[nt][2] + bdv1.x;
                float v3 = s[nt][3] + bdv1.y;
                if (qc == 0 && ch == 7 && nt == 15 && wid == 0 && lane == 3) v1 += wrapv;
                v0 *= 0.125f; v1 *= 0.125f; v2 *= 0.125f; v3 *= 0.125f;
                if (mq0a[nt].x) v0 = -10000.f;
                if (mq0a[nt].y) v1 = -10000.f;
                if (mq1a[nt].x) v2 = -10000.f;
                if (mq1a[nt].y) v3 = -10000.f;
                s[nt][0]=v0; s[nt][1]=v1; s[nt][2]=v2; s[nt][3]=v3;
                mc0 = fmaxf(mc0, fmaxf(v0, v1));
                mc1 = fmaxf(mc1, fmaxf(v2, v3));
            }
            mc0 = fmaxf(mc0, __shfl_xor_sync(0xffffffffu, mc0, 1));
            mc0 = fmaxf(mc0, __shfl_xor_sync(0xffffffffu, mc0, 2));
            mc1 = fmaxf(mc1, __shfl_xor_sync(0xffffffffu, mc1, 1));
            mc1 = fmaxf(mc1, __shfl_xor_sync(0xffffffffu, mc1, 2));
            float mn0 = fmaxf(m0, mc0), mn1 = fmaxf(m1, mc1);
            float cor0 = __expf(m0 - mn0), cor1 = __expf(m1 - mn1);
            m0 = mn0; m1 = mn1;
            float ls0 = 0.f, ls1 = 0.f;
            uint32_t paF[8][4];
            #pragma unroll
            for (int kt = 0; kt < 8; ++kt) {
                float p00 = __expf(s[2*kt][0]   - m0), p01 = __expf(s[2*kt][1]   - m0);
                float p02 = __expf(s[2*kt][2]   - m1), p03 = __expf(s[2*kt][3]   - m1);
                float p10 = __expf(s[2*kt+1][0] - m0), p11 = __expf(s[2*kt+1][1] - m0);
                float p12 = __expf(s[2*kt+1][2] - m1), p13 = __expf(s[2*kt+1][3] - m1);
                ls0 += p00 + p01 + p10 + p11;
                ls1 += p02 + p03 + p12 + p13;
                paF[kt][0] = packh(p00, p01);
                paF[kt][1] = packh(p02, p03);
                paF[kt][2] = packh(p10, p11);
                paF[kt][3] = packh(p12, p13);
            }
            ls0 += __shfl_xor_sync(0xffffffffu, ls0, 1);
            ls0 += __shfl_xor_sync(0xffffffffu, ls0, 2);
            ls1 += __shfl_xor_sync(0xffffffffu, ls1, 1);
            ls1 += __shfl_xor_sync(0xffffffffu, ls1, 2);
            l0 = l0*cor0 + ls0;
            l1 = l1*cor1 + ls1;
            #pragma unroll
            for (int dn = 0; dn < 8; ++dn) {
                accO[dn][0]*=cor0; accO[dn][1]*=cor0; accO[dn][2]*=cor1; accO[dn][3]*=cor1;
            }
            #pragma unroll
            for (int kt = 0; kt < 8; ++kt) {
                #pragma unroll
                for (int dp = 0; dp < 4; ++dp) {
                    uint32_t bF[4];
                    ldsm4t(bF, v_addr(sb + AV_BUF, kt*16, dp*16, lane));
                    mma16816(accO[2*dp],   paF[kt], &bF[0]);
                    mma16816(accO[2*dp+1], paF[kt], &bF[2]);
                }
            }
        }

        __syncthreads();
        if (st + 2 < 16) issue(st + 2);
        CP_COMMIT();
    }

    float inv0 = 1.f / l0, inv1 = 1.f / l1;
    const int q0 = qc + wq + r, q1 = q0 + 8;
    #pragma unroll
    for (int dn = 0; dn < 8; ++dn) {
        int d = dn*8 + c;
        *(uint32_t*)(tf + (size_t)(b*SS_+q0)*DD + h*DKK + d) = packh(accO[dn][0]*inv0, accO[dn][1]*inv0);
        *(uint32_t*)(tf + (size_t)(b*SS_+q1)*DD + h*DKK + d) = packh(accO[dn][2]*inv1, accO[dn][3]*inv1);
    }
}

// ---------------- launch ----------------
extern "C" void kernel_launch(void* const* d_in, const int* in_sizes, int n_in,
                              void* d_out, int out_size) {
    const float* inputs        = (const float*)d_in[0];
    const unsigned char* amask = (const unsigned char*)d_in[1];
    const float* Wq = (const float*)d_in[2];
    const float* bq = (const float*)d_in[3];
    const float* Wk = (const float*)d_in[4];
    const float* bk = (const float*)d_in[5];
    const float* Wv = (const float*)d_in[6];
    const float* bv = (const float*)d_in[7];
    const float* Wo = (const float*)d_in[8];
    const float* bo = (const float*)d_in[9];
    const float* Wp = (const float*)d_in[10];
    const float* pu = (const float*)d_in[11];
    const float* pv = (const float*)d_in[12];
    const float* gamma = (const float*)d_in[13];
    const float* beta  = (const float*)d_in[14];
    float* out = (float*)d_out;

    half_t *xf,*pef,*wf,*quf,*qvf,*kf,*vf,*pf,*tf;
    cudaGetSymbolAddress((void**)&xf, g_xf);
    cudaGetSymbolAddress((void**)&pef, g_pef);
    cudaGetSymbolAddress((void**)&wf, g_wf);
    cudaGetSymbolAddress((void**)&quf, g_quf);
    cudaGetSymbolAddress((void**)&qvf, g_qvf);
    cudaGetSymbolAddress((void**)&kf, g_kf);
    cudaGetSymbolAddress((void**)&vf, g_vf);
    cudaGetSymbolAddress((void**)&pf, g_pf);
    cudaGetSymbolAddress((void**)&tf, g_tf);

    cudaFuncSetAttribute(proj_all,   cudaFuncAttributeMaxDynamicSharedMemorySize, 65536);
    cudaFuncSetAttribute(gemm_out,   cudaFuncAttributeMaxDynamicSharedMemorySize, 98304);
    cudaFuncSetAttribute(attn_fused, cudaFuncAttributeMaxDynamicSharedMemorySize, ASMEM);

    prep_kernel<<<5376, 256>>>(inputs, gamma, beta, Wq, Wk, Wv, Wo, Wp, xf, pef, wf);
    proj_all<<<448, 256, 65536>>>(xf, pef, wf, bq, bk, bv, pu, pv, quf, qvf, kf, vf, pf);
    attn_fused<<<dim3(16, BB*HH), 128, ASMEM>>>(quf, qvf, kf, vf, pf, amask, tf);
    gemm_out<<<dim3(4,32), 256, 98304>>>(tf, wf+3*(size_t)DD*DD, bo, out);

    (void)in_sizes; (void)n_in; (void)out_size;
}

// round 15
// speedup vs baseline: 1.0034x; 1.0034x over previous
#include <cuda_runtime.h>
#include <cuda_fp16.h>
#include <math.h>
#include <string.h>
#include <stdint.h>

#define BB 4
#define SS_ 1024
#define DD 512
#define HH 8
#define DKK 64
#define PP_ 2047
#define PPAD 2048
#define PBAND 2304

typedef __half half_t;

// ---------------- scratch (zero-initialized device globals) ----------------
__device__ half_t g_xf[BB*SS_*DD];
__device__ half_t g_pef[PPAD*DD];
__device__ half_t g_wf[5*DD*DD];
__device__ half_t g_quf[BB*SS_*DD], g_qvf[BB*SS_*DD];
__device__ half_t g_kf[BB*SS_*DD],  g_vf[BB*SS_*DD];
__device__ half_t g_pf[(size_t)PBAND*DD];   // rows >= 2047 stay zero
__device__ half_t g_tf[BB*SS_*DD];

// ---------------- helpers ----------------
__device__ __forceinline__ void mma16816(float* d, const uint32_t* a, const uint32_t* b){
    asm volatile("mma.sync.aligned.m16n8k16.row.col.f32.f16.f16.f32 "
        "{%0,%1,%2,%3}, {%4,%5,%6,%7}, {%8,%9}, {%0,%1,%2,%3};"
        : "+f"(d[0]),"+f"(d[1]),"+f"(d[2]),"+f"(d[3])
        : "r"(a[0]),"r"(a[1]),"r"(a[2]),"r"(a[3]), "r"(b[0]),"r"(b[1]));
}
__device__ __forceinline__ void ldsm4(uint32_t* r, uint32_t addr){
    asm volatile("ldmatrix.sync.aligned.m8n8.x4.shared.b16 {%0,%1,%2,%3}, [%4];"
        :"=r"(r[0]),"=r"(r[1]),"=r"(r[2]),"=r"(r[3]):"r"(addr));
}
__device__ __forceinline__ void ldsm4t(uint32_t* r, uint32_t addr){
    asm volatile("ldmatrix.sync.aligned.m8n8.x4.trans.shared.b16 {%0,%1,%2,%3}, [%4];"
        :"=r"(r[0]),"=r"(r[1]),"=r"(r[2]),"=r"(r[3]):"r"(addr));
}
__device__ __forceinline__ uint32_t smem_u32(const void* p){
    uint32_t a; asm("{ .reg .u64 t; cvta.to.shared.u64 t, %1; cvt.u32.u64 %0, t; }":"=r"(a):"l"(p)); return a;
}
__device__ __forceinline__ void cp16(uint32_t dst, const void* src){
    asm volatile("cp.async.cg.shared.global [%0], [%1], 16;"
        :: "r"(dst), "l"(__cvta_generic_to_global(src)));
}
#define CP_COMMIT() asm volatile("cp.async.commit_group;" ::: "memory")
#define CP_WAIT1()  asm volatile("cp.async.wait_group 1;" ::: "memory")
#define CP_WAIT2()  asm volatile("cp.async.wait_group 2;" ::: "memory")
static __device__ __forceinline__ uint32_t swz(uint32_t o){ return o ^ ((o>>3)&0x70); }
__device__ __forceinline__ uint32_t a_addr(uint32_t base, int m16, int k0, int lane){
    int g = lane>>3, r = lane&7;
    int row = m16 + r + (g&1)*8;
    uint32_t o = (uint32_t)(row*128 + (k0 + (g>>1)*8)*2);
    return base + swz(o);
}
__device__ __forceinline__ uint32_t b_addr(uint32_t base, int n0, int k0, int lane){
    int g = lane>>3, r = lane&7;
    int row = n0 + r + (g>>1)*8;
    uint32_t o = (uint32_t)(row*128 + (k0 + (g&1)*8)*2);
    return base + swz(o);
}
__device__ __forceinline__ uint32_t v_addr(uint32_t base, int k0, int d0, int lane){
    int g = lane>>3, r = lane&7;
    int row = k0 + r + (g&1)*8;
    uint32_t o = (uint32_t)(row*128 + (d0 + (g>>1)*8)*2);
    return base + swz(o);
}
__device__ __forceinline__ uint32_t packh(float x, float y){
    __half2 h = __floats2half2_rn(x, y);
    uint32_t u; memcpy(&u, &h, 4); return u;
}

// ================= prep: LN + PE + weight converts, one launch =================
__global__ void prep_kernel(const float* __restrict__ x, const float* __restrict__ gamma,
                            const float* __restrict__ beta,
                            const float* __restrict__ Wq, const float* __restrict__ Wk,
                            const float* __restrict__ Wv, const float* __restrict__ Wo,
                            const float* __restrict__ Wp,
                            half_t* __restrict__ xf, half_t* __restrict__ pef,
                            half_t* __restrict__ wf) {
    __shared__ float red[8];
    const int blk = blockIdx.x, tid = threadIdx.x;
    if (blk < 2048) {
        int halfid = tid >> 7, t = tid & 127;
        int row = blk*2 + halfid;
        float4 v = ((const float4*)(x + (size_t)row*DD))[t];
        float s = v.x+v.y+v.z+v.w;
        #pragma unroll
        for (int o=16;o;o>>=1) s += __shfl_xor_sync(0xffffffffu,s,o);
        if ((t&31)==0) red[tid>>5]=s;
        __syncthreads();
        float mu=(red[halfid*4]+red[halfid*4+1]+red[halfid*4+2]+red[halfid*4+3])*(1.0f/DD);
        float dx=v.x-mu,dy=v.y-mu,dz=v.z-mu,dw=v.w-mu;
        float ss=dx*dx+dy*dy+dz*dz+dw*dw;
        #pragma unroll
        for (int o=16;o;o>>=1) ss += __shfl_xor_sync(0xffffffffu,ss,o);
        __syncthreads();
        if ((t&31)==0) red[tid>>5]=ss;
        __syncthreads();
        float rstd=rsqrtf((red[halfid*4]+red[halfid*4+1]+red[halfid*4+2]+red[halfid*4+3])*(1.0f/DD)+1e-5f);
        float4 g=((const float4*)gamma)[t], be=((const float4*)beta)[t];
        uint2 o2;
        o2.x = packh(dx*rstd*g.x+be.x, dy*rstd*g.y+be.y);
        o2.y = packh(dz*rstd*g.z+be.z, dw*rstd*g.w+be.w);
        *(uint2*)(xf + (size_t)row*DD + 4*t) = o2;
    } else if (blk < 4096) {
        int j = blk - 2048;
        uint32_t u = 0;
        if (j < PP_) {
            float pos = (float)(j - (SS_ - 1));
            const float kconst = -0.01798894603901598415f;
            float div = expf((float)(2*tid) * kconst);
            float sa, ca; sincosf(pos * div, &sa, &ca);
            u = packh(sa, ca);
        }
        *(uint32_t*)(pef + (size_t)j*DD + 2*tid) = u;
    } else {
        int i = (blk - 4096)*256 + tid;
        int widx = i >> 16, j = i & 65535;
        const float* src = (widx==0)?Wq:(widx==1)?Wk:(widx==2)?Wv:(widx==3)?Wo:Wp;
        float4 v = ((const float4*)src)[j];
        uint2 o2; o2.x = packh(v.x, v.y); o2.y = packh(v.z, v.w);
        ((uint2*)(wf + (size_t)widx*DD*DD))[j] = o2;
    }
}

// ================= fused projections: QKV (N=1536) + P, 2-stage (best) =================
__global__ __launch_bounds__(256,2) void proj_all(
    const half_t* __restrict__ xf, const half_t* __restrict__ pef,
    const half_t* __restrict__ wf,
    const float* __restrict__ bq, const float* __restrict__ bk, const float* __restrict__ bv,
    const float* __restrict__ pu, const float* __restrict__ pv,
    half_t* __restrict__ quf, half_t* __restrict__ qvf,
    half_t* __restrict__ kf, half_t* __restrict__ vf, half_t* __restrict__ pf)
{
    extern __shared__ char sm[];
    const int tid = threadIdx.x, lane = tid & 31, wid = tid >> 5;
    const uint32_t sb = smem_u32(sm);
    const int m0w = (wid>>2)*64, n0w = (wid&3)*32;
    const int cta = blockIdx.x;
    const half_t *A, *B;
    int bm, bn, mode;
    if (cta < 384) {
        int bx = cta % 12, by = cta / 12;
        bm = by*128; bn = bx*128;
        A = xf; B = wf + (size_t)bn*DD;
        mode = bn >> 9;
    } else {
        int c2 = cta - 384;
        int bx = c2 & 3, by = c2 >> 2;
        bm = by*128; bn = bx*128;
        A = pef; B = wf + 4*(size_t)DD*DD + (size_t)bn*DD;
        mode = 3;
    }

    auto issueg = [&](int kc){
        uint32_t base = sb + (uint32_t)(kc&1)*32768;
        for (int u = tid; u < 1024; u += 256) {
            int row = u>>3, cb = u&7;
            uint32_t off = swz((uint32_t)(row*128 + cb*16));
            cp16(base + off,         A + (size_t)(bm+row)*DD + kc*64 + cb*8);
            cp16(base + 16384 + off, B + (size_t)row*DD + kc*64 + cb*8);
        }
    };

    float acc[4][4][4];
    #pragma unroll
    for (int a=0;a<4;++a)
        #pragma unroll
        for (int b2=0;b2<4;++b2)
            #pragma unroll
            for (int c2=0;c2<4;++c2) acc[a][b2][c2]=0.f;

    issueg(0); CP_COMMIT();
    issueg(1); CP_COMMIT();

    for (int kc = 0; kc < 8; ++kc) {
        CP_WAIT1();
        __syncthreads();
        uint32_t base = sb + (uint32_t)(kc&1)*32768;
        #pragma unroll
        for (int ks = 0; ks < 4; ++ks) {
            int k0 = ks*16;
            uint32_t aF[4][4], bF[2][4];
            #pragma unroll
            for (int mt=0; mt<4; ++mt) ldsm4(aF[mt], a_addr(base, m0w+mt*16, k0, lane));
            #pragma unroll
            for (int p=0; p<2; ++p)   ldsm4(bF[p], b_addr(base+16384, n0w+p*16, k0, lane));
            #pragma unroll
            for (int mt=0; mt<4; ++mt)
                #pragma unroll
                for (int nt=0; nt<4; ++nt)
                    mma16816(acc[mt][nt], aF[mt], &bF[nt>>1][(nt&1)*2]);
        }
        __syncthreads();
        if (kc + 2 < 8) issueg(kc + 2);
        CP_COMMIT();
    }
    const int r = lane>>2, c = (lane&3)*2;
    const int nbase = bn & 511;
    #pragma unroll
    for (int mt=0; mt<4; ++mt)
        #pragma unroll
        for (int nt=0; nt<4; ++nt) {
            int nl = nbase + n0w + nt*8 + c;
            float b0 = 0.f, b1 = 0.f;
            if (mode == 0)      { b0 = bq[nl]; b1 = bq[nl+1]; }
            else if (mode == 1) { b0 = bk[nl]; b1 = bk[nl+1]; }
            else if (mode == 2) { b0 = bv[nl]; b1 = bv[nl+1]; }
            #pragma unroll
            for (int half_=0; half_<2; ++half_) {
                int m_ = bm + m0w + mt*16 + r + half_*8;
                float v0 = acc[mt][nt][half_*2+0] + b0;
                float v1 = acc[mt][nt][half_*2+1] + b1;
                if (mode == 0) {
                    *(uint32_t*)(quf + (size_t)m_*DD + nl) = packh(v0 + pu[nl], v1 + pu[nl+1]);
                    *(uint32_t*)(qvf + (size_t)m_*DD + nl) = packh(v0 + pv[nl], v1 + pv[nl+1]);
                } else if (mode == 1) {
                    *(uint32_t*)(kf + (size_t)m_*DD + nl) = packh(v0, v1);
                } else if (mode == 2) {
                    *(uint32_t*)(vf + (size_t)m_*DD + nl) = packh(v0, v1);
                } else {
                    *(uint32_t*)(pf + (size_t)m_*DD + nl) = packh(v0, v1);
                }
            }
        }
}

// ================= out projection: 128x128 tiles, 3-stage (best) =================
__global__ __launch_bounds__(256,2) void gemm_out(
    const half_t* __restrict__ A, const half_t* __restrict__ Bw,
    const float* __restrict__ bias, float* __restrict__ O32)
{
    extern __shared__ char sm[];
    const int tid = threadIdx.x, lane = tid & 31, wid = tid >> 5;
    const int bm = blockIdx.y * 128, bn = blockIdx.x * 128;
    const uint32_t sb = smem_u32(sm);
    const int m0w = (wid>>2)*64, n0w = (wid&3)*32;

    auto issueg = [&](int kc){
        uint32_t base = sb + (uint32_t)(kc%3)*32768;
        for (int u = tid; u < 1024; u += 256) {
            int row = u>>3, cb = u&7;
            uint32_t off = swz((uint32_t)(row*128 + cb*16));
            cp16(base + off,         A  + (size_t)(bm+row)*DD + kc*64 + cb*8);
            cp16(base + 16384 + off, Bw + (size_t)(bn+row)*DD + kc*64 + cb*8);
        }
    };

    float acc[4][4][4];
    #pragma unroll
    for (int a=0;a<4;++a)
        #pragma unroll
        for (int b2=0;b2<4;++b2)
            #pragma unroll
            for (int c2=0;c2<4;++c2) acc[a][b2][c2]=0.f;

    issueg(0); CP_COMMIT();
    issueg(1); CP_COMMIT();
    issueg(2); CP_COMMIT();

    for (int kc = 0; kc < 8; ++kc) {
        CP_WAIT2();
        __syncthreads();
        uint32_t base = sb + (uint32_t)(kc%3)*32768;
        #pragma unroll
        for (int ks = 0; ks < 4; ++ks) {
            int k0 = ks*16;
            uint32_t aF[4][4], bF[2][4];
            #pragma unroll
            for (int mt=0; mt<4; ++mt) ldsm4(aF[mt], a_addr(base, m0w+mt*16, k0, lane));
            #pragma unroll
            for (int p=0; p<2; ++p)   ldsm4(bF[p], b_addr(base+16384, n0w+p*16, k0, lane));
            #pragma unroll
            for (int mt=0; mt<4; ++mt)
                #pragma unroll
                for (int nt=0; nt<4; ++nt)
                    mma16816(acc[mt][nt], aF[mt], &bF[nt>>1][(nt&1)*2]);
        }
        __syncthreads();
        if (kc + 3 < 8) issueg(kc + 3);
        CP_COMMIT();
    }
    const int r = lane>>2, c = (lane&3)*2;
    #pragma unroll
    for (int mt=0; mt<4; ++mt)
        #pragma unroll
        for (int nt=0; nt<4; ++nt) {
            int n_ = bn + n0w + nt*8 + c;
            float b0 = bias[n_], b1 = bias[n_+1];
            #pragma unroll
            for (int half_=0; half_<2; ++half_) {
                int m_ = bm + m0w + mt*16 + r + half_*8;
                *(float2*)(O32 + (size_t)m_*DD + n_) =
                    make_float2(acc[mt][nt][half_*2+0] + b0, acc[mt][nt][half_*2+1] + b1);
            }
        }
}

// ================= fused attention: 64-row q-tiles, 128 thr, 2 CTA/SM =================
#define AQ_V   8192
#define AP_BUF 16384
#define AK_BUF 40960
#define AV_BUF 57344
#define ABD    73728
#define ASMEM  107520
__global__ __launch_bounds__(128,2) void attn_fused(
    const half_t* __restrict__ quf, const half_t* __restrict__ qvf,
    const half_t* __restrict__ kf,  const half_t* __restrict__ vf,
    const half_t* __restrict__ pf,
    const unsigned char* __restrict__ mask,
    half_t* __restrict__ tf)
{
    extern __shared__ char sm[];
    const int tid = threadIdx.x, lane = tid & 31, wid = tid >> 5;
    const int bh = blockIdx.y, b = bh >> 3, h = bh & 7;
    const int qc = blockIdx.x * 64;
    const uint32_t sb = smem_u32(sm);
    float* bd = (float*)(sm + ABD);
    const int wq = wid * 16;
    const int r = lane>>2, c = (lane&3)*2;

    auto issue = [&](int st){
        int ch = st >> 1;
        if ((st & 1) == 0) {
            size_t rowbase = (size_t)(1024 + 128*ch - qc - 63);
            for (int u = tid; u < 1536; u += 128){
                int row = u>>3, cb = u&7;
                cp16(sb + AP_BUF + swz((uint32_t)(row*128 + cb*16)),
                     pf + (rowbase + row)*DD + h*DKK + cb*8);
            }
        } else {
            size_t rowbase = (size_t)(b*SS_ + 128*ch);
            for (int u = tid; u < 1024; u += 128){
                int row = u>>3, cb = u&7;
                uint32_t off = swz((uint32_t)(row*128 + cb*16));
                cp16(sb + AK_BUF + off, kf + (rowbase + row)*DD + h*DKK + cb*8);
                cp16(sb + AV_BUF + off, vf + (rowbase + row)*DD + h*DKK + cb*8);
            }
        }
    };

    for (int u = tid; u < 512; u += 128) {
        int row = u>>3, cb = u&7;
        uint32_t off = swz((uint32_t)(row*128 + cb*16));
        size_t g = (size_t)(b*SS_ + qc + row)*DD + h*DKK + cb*8;
        cp16(sb + off,        quf + g);
        cp16(sb + AQ_V + off, qvf + g);
    }
    issue(0); CP_COMMIT();
    issue(1); CP_COMMIT();

    float wrapv = 0.f;
    if (qc == 0 && wid == 0) {
        #pragma unroll
        for (int d = 0; d < DKK; ++d)
            wrapv += __half2float(qvf[(size_t)(b*SS_+1)*DD + h*DKK + d])
                   * __half2float(pf[h*DKK + d]);
    }

    float m0 = -1e30f, m1 = -1e30f, l0 = 0.f, l1 = 0.f;
    float accO[8][4];
    #pragma unroll
    for (int i=0;i<8;++i)
        #pragma unroll
        for (int j=0;j<4;++j) accO[i][j]=0.f;

    const int i0 = wq + r, i1 = i0 + 8;
    const int bd0base = i0*132, bd1base = i1*132;

    for (int st = 0; st < 16; ++st) {
        CP_WAIT1();
        __syncthreads();
        const int ch = st >> 1;

        if ((st & 1) == 0) {
            float bdacc[9][2][4];
            #pragma unroll
            for (int gi=0;gi<9;++gi)
                #pragma unroll
                for (int q2=0;q2<2;++q2)
                    #pragma unroll
                    for (int e=0;e<4;++e) bdacc[gi][q2][e]=0.f;
            #pragma unroll
            for (int ks = 0; ks < 4; ++ks) {
                int k0 = ks*16;
                uint32_t aF[4];
                ldsm4(aF, a_addr(sb + AQ_V, wq, k0, lane));
                #pragma unroll
                for (int gi = 0; gi < 9; ++gi) {
                    int n0 = (3 - wid + gi)*16;
                    uint32_t bF[4];
                    ldsm4(bF, b_addr(sb + AP_BUF, n0, k0, lane));
                    mma16816(bdacc[gi][0], aF, &bF[0]);
                    mma16816(bdacc[gi][1], aF, &bF[2]);
                }
            }
            #pragma unroll
            for (int gi = 0; gi < 9; ++gi) {
                int g16 = 3 - wid + gi;
                #pragma unroll
                for (int q2 = 0; q2 < 2; ++q2) {
                    int t0 = g16*16 + q2*8 + c;
                    int j;
                    j = t0     + i0 - 63; if (j>=0 && j<128) bd[bd0base+j] = bdacc[gi][q2][0];
                    j = t0 + 1 + i0 - 63; if (j>=0 && j<128) bd[bd0base+j] = bdacc[gi][q2][1];
                    j = t0     + i1 - 63; if (j>=0 && j<128) bd[bd1base+j] = bdacc[gi][q2][2];
                    j = t0 + 1 + i1 - 63; if (j>=0 && j<128) bd[bd1base+j] = bdacc[gi][q2][3];
                }
            }
        } else {
            const int kk0 = ch * 128;

            // hoisted mask prefetch
            uchar2 mq0a[16], mq1a[16];
            {
                const unsigned char* mb0 = mask + (size_t)b*SS_*SS_ + (size_t)(qc+i0)*SS_ + kk0;
                const unsigned char* mb1 = mask + (size_t)b*SS_*SS_ + (size_t)(qc+i1)*SS_ + kk0;
                #pragma unroll
                for (int nt = 0; nt < 16; ++nt) {
                    int jc = nt*8 + c;
                    mq0a[nt] = *(const uchar2*)(mb0 + jc);
                    mq1a[nt] = *(const uchar2*)(mb1 + jc);
                }
            }

            float s[16][4];
            #pragma unroll
            for (int nt=0;nt<16;++nt)
                #pragma unroll
                for (int e=0;e<4;++e) s[nt][e]=0.f;
            #pragma unroll
            for (int ks = 0; ks < 4; ++ks) {
                int k0 = ks*16;
                uint32_t aF[4];
                ldsm4(aF, a_addr(sb, wq, k0, lane));
                #pragma unroll
                for (int g16 = 0; g16 < 8; ++g16) {
                    uint32_t bF[4];
                    ldsm4(bF, b_addr(sb + AK_BUF, g16*16, k0, lane));
                    mma16816(s[2*g16],   aF, &bF[0]);
                    mma16816(s[2*g16+1], aF, &bF[2]);
                }
            }
            float mc0 = -1e30f, mc1 = -1e30f;
            #pragma unroll
            for (int nt = 0; nt < 16; ++nt) {
                int jc = nt*8 + c;
                float2 bdv0 = *(const float2*)&bd[bd0base + jc];
                float2 bdv1 = *(const float2*)&bd[bd1base + jc];
                float v0 = s[nt][0] + bdv0.x;
                float v1 = s[nt][1] + bdv0.y;
                float v2 = s[nt][2] + bdv1.x;
                float v3 = s[nt][3] + bdv1.y;
                if (qc == 0 && ch == 7 && nt == 15 && wid == 0 && lane == 3) v1 += wrapv;
                v0 *= 0.125f; v1 *= 0.125f; v2 *= 0.125f; v3 *= 0.125f;
                if (mq0a[nt].x) v0 = -10000.f;
                if (mq0a[nt].y) v1 = -10000.f;
                if (mq1a[nt].x) v2 = -10000.f;
                if (mq1a[nt].y) v3 = -10000.f;
                s[nt][0]=v0; s[nt][1]=v1; s[nt][2]=v2; s[nt][3]=v3;
                mc0 = fmaxf(mc0, fmaxf(v0, v1));
                mc1 = fmaxf(mc1, fmaxf(v2, v3));
            }
            mc0 = fmaxf(mc0, __shfl_xor_sync(0xffffffffu, mc0, 1));
            mc0 = fmaxf(mc0, __shfl_xor_sync(0xffffffffu, mc0, 2));
            mc1 = fmaxf(mc1, __shfl_xor_sync(0xffffffffu, mc1, 1));
            mc1 = fmaxf(mc1, __shfl_xor_sync(0xffffffffu, mc1, 2));
            float mn0 = fmaxf(m0, mc0), mn1 = fmaxf(m1, mc1);
            float cor0 = __expf(m0 - mn0), cor1 = __expf(m1 - mn1);
            m0 = mn0; m1 = mn1;
            #pragma unroll
            for (int dn = 0; dn < 8; ++dn) {
                accO[dn][0]*=cor0; accO[dn][1]*=cor0; accO[dn][2]*=cor1; accO[dn][3]*=cor1;
            }
            // fused exp/pack + PV per kt: MUFU for kt+1 overlaps HMMA for kt
            float ls0 = 0.f, ls1 = 0.f;
            #pragma unroll
            for (int kt = 0; kt < 8; ++kt) {
                float p00 = __expf(s[2*kt][0]   - m0), p01 = __expf(s[2*kt][1]   - m0);
                float p02 = __expf(s[2*kt][2]   - m1), p03 = __expf(s[2*kt][3]   - m1);
                float p10 = __expf(s[2*kt+1][0] - m0), p11 = __expf(s[2*kt+1][1] - m0);
                float p12 = __expf(s[2*kt+1][2] - m1), p13 = __expf(s[2*kt+1][3] - m1);
                ls0 += p00 + p01 + p10 + p11;
                ls1 += p02 + p03 + p12 + p13;
                uint32_t paF[4];
                paF[0] = packh(p00, p01);
                paF[1] = packh(p02, p03);
                paF[2] = packh(p10, p11);
                paF[3] = packh(p12, p13);
                #pragma unroll
                for (int dp = 0; dp < 4; ++dp) {
                    uint32_t bF[4];
                    ldsm4t(bF, v_addr(sb + AV_BUF, kt*16, dp*16, lane));
                    mma16816(accO[2*dp],   paF, &bF[0]);
                    mma16816(accO[2*dp+1], paF, &bF[2]);
                }
            }
            ls0 += __shfl_xor_sync(0xffffffffu, ls0, 1);
            ls0 += __shfl_xor_sync(0xffffffffu, ls0, 2);
            ls1 += __shfl_xor_sync(0xffffffffu, ls1, 1);
            ls1 += __shfl_xor_sync(0xffffffffu, ls1, 2);
            l0 = l0*cor0 + ls0;
            l1 = l1*cor1 + ls1;
        }

        __syncthreads();
        if (st + 2 < 16) issue(st + 2);
        CP_COMMIT();
    }

    float inv0 = 1.f / l0, inv1 = 1.f / l1;
    const int q0 = qc + wq + r, q1 = q0 + 8;
    #pragma unroll
    for (int dn = 0; dn < 8; ++dn) {
        int d = dn*8 + c;
        *(uint32_t*)(tf + (size_t)(b*SS_+q0)*DD + h*DKK + d) = packh(accO[dn][0]*inv0, accO[dn][1]*inv0);
        *(uint32_t*)(tf + (size_t)(b*SS_+q1)*DD + h*DKK + d) = packh(accO[dn][2]*inv1, accO[dn][3]*inv1);
    }
}

// ---------------- launch ----------------
extern "C" void kernel_launch(void* const* d_in, const int* in_sizes, int n_in,
                              void* d_out, int out_size) {
    const float* inputs        = (const float*)d_in[0];
    const unsigned char* amask = (const unsigned char*)d_in[1];
    const float* Wq = (const float*)d_in[2];
    const float* bq = (const float*)d_in[3];
    const float* Wk = (const float*)d_in[4];
    const float* bk = (const float*)d_in[5];
    const float* Wv = (const float*)d_in[6];
    const float* bv = (const float*)d_in[7];
    const float* Wo = (const float*)d_in[8];
    const float* bo = (const float*)d_in[9];
    const float* Wp = (const float*)d_in[10];
    const float* pu = (const float*)d_in[11];
    const float* pv = (const float*)d_in[12];
    const float* gamma = (const float*)d_in[13];
    const float* beta  = (const float*)d_in[14];
    float* out = (float*)d_out;

    half_t *xf,*pef,*wf,*quf,*qvf,*kf,*vf,*pf,*tf;
    cudaGetSymbolAddress((void**)&xf, g_xf);
    cudaGetSymbolAddress((void**)&pef, g_pef);
    cudaGetSymbolAddress((void**)&wf, g_wf);
    cudaGetSymbolAddress((void**)&quf, g_quf);
    cudaGetSymbolAddress((void**)&qvf, g_qvf);
    cudaGetSymbolAddress((void**)&kf, g_kf);
    cudaGetSymbolAddress((void**)&vf, g_vf);
    cudaGetSymbolAddress((void**)&pf, g_pf);
    cudaGetSymbolAddress((void**)&tf, g_tf);

    cudaFuncSetAttribute(proj_all,   cudaFuncAttributeMaxDynamicSharedMemorySize, 65536);
    cudaFuncSetAttribute(gemm_out,   cudaFuncAttributeMaxDynamicSharedMemorySize, 98304);
    cudaFuncSetAttribute(attn_fused, cudaFuncAttributeMaxDynamicSharedMemorySize, ASMEM);

    prep_kernel<<<5376, 256>>>(inputs, gamma, beta, Wq, Wk, Wv, Wo, Wp, xf, pef, wf);
    proj_all<<<448, 256, 65536>>>(xf, pef, wf, bq, bk, bv, pu, pv, quf, qvf, kf, vf, pf);
    attn_fused<<<dim3(16, BB*HH), 128, ASMEM>>>(quf, qvf, kf, vf, pf, amask, tf);
    gemm_out<<<dim3(4,32), 256, 98304>>>(tf, wf+3*(size_t)DD*DD, bo, out);

    (void)in_sizes; (void)n_in; (void)out_size;
}